// round 1
// baseline (speedup 1.0000x reference)
#include <cuda_runtime.h>
#include <math.h>

// Problem constants
#define BB   4096
#define TT   64
#define DD   100
#define FF   50
#define LL   64
#define NUU  64
#define KK   128
#define GII  114   // F + L
#define RB   32    // rows per CTA
#define NTHR 256

// ---- shared memory layout (floats) ----
#define S_WU1 0
#define S_WR1 (S_WU1 + GII*64)        // 7296
#define S_WN1 (S_WR1 + GII*64)        // 14592
#define S_WO1 (S_WN1 + GII*64)        // 21888
#define S_WU2 (S_WO1 + 64*64)         // 25984
#define S_WR2 (S_WU2 + 64*64)         // 30080
#define S_WN2 (S_WR2 + 64*64)         // 34176
#define S_WO2 (S_WN2 + 64*64)         // 38272
#define S_WD  (S_WO2 + 64*64)         // 42368
#define S_BU1 (S_WD + 64)             // 42432
#define S_BU2 (S_BU1 + 64)
#define S_BR1 (S_BU2 + 64)
#define S_BR2 (S_BR1 + 64)
#define S_BN1 (S_BR2 + 64)
#define S_BN2 (S_BN1 + 64)
#define S_BO1 (S_BN2 + 64)
#define S_BO2 (S_BO1 + 64)
#define S_Y   (S_BO2 + 64)            // 42944
#define S_Y1  (S_Y  + 64*RB)          // 44992
#define S_H   (S_Y1 + 64*RB)          // 47040
#define S_U   (S_H  + 64*RB)          // 49088
#define S_YC  (S_U  + 64*RB)          // 51136  (114 x 32)
#define S_PV  (S_YC + GII*RB)         // 54784  (8 x 32 vol partials)
#define S_END (S_PV + 8*32)           // 55040 floats
#define SMEM_BYTES (S_END * 4)        // 220160 bytes

// scratch: per-row per-step volume output
__device__ float g_vol[BB * KK];

__device__ __forceinline__ float sigm(float x) {
    return 1.0f / (1.0f + expf(-x));
}

// C[32 rows x 64 cols] += A[KI x 32] * W[KI x 64]; thread tile 2 rows x 4 cols.
template<int KI>
__device__ __forceinline__ void mm8(const float* __restrict__ A,
                                    const float* __restrict__ W,
                                    int r0, int c0, float (&acc)[4][2]) {
#pragma unroll
    for (int c = 0; c < 4; ++c) { acc[c][0] = 0.f; acc[c][1] = 0.f; }
#pragma unroll 2
    for (int i = 0; i < KI; ++i) {
        float2 a = *reinterpret_cast<const float2*>(A + i * RB + r0);
        float4 w = *reinterpret_cast<const float4*>(W + i * 64 + c0);
        acc[0][0] = fmaf(a.x, w.x, acc[0][0]);
        acc[0][1] = fmaf(a.y, w.x, acc[0][1]);
        acc[1][0] = fmaf(a.x, w.y, acc[1][0]);
        acc[1][1] = fmaf(a.y, w.y, acc[1][1]);
        acc[2][0] = fmaf(a.x, w.z, acc[2][0]);
        acc[2][1] = fmaf(a.y, w.z, acc[2][1]);
        acc[3][0] = fmaf(a.x, w.w, acc[3][0]);
        acc[3][1] = fmaf(a.y, w.w, acc[3][1]);
    }
}

__global__ void __launch_bounds__(NTHR, 1) lobrm_main(
    const float* __restrict__ data, const int* __restrict__ tsteps,
    const float* __restrict__ Wu1, const float* __restrict__ bu1,
    const float* __restrict__ Wu2, const float* __restrict__ bu2,
    const float* __restrict__ Wr1, const float* __restrict__ br1,
    const float* __restrict__ Wr2, const float* __restrict__ br2,
    const float* __restrict__ Wn1, const float* __restrict__ bn1,
    const float* __restrict__ Wn2, const float* __restrict__ bn2,
    const float* __restrict__ Wo1, const float* __restrict__ bo1,
    const float* __restrict__ Wo2, const float* __restrict__ bo2,
    const float* __restrict__ Wd,  const float* __restrict__ bd,
    float* __restrict__ out_prevy)
{
    extern __shared__ float sm[];
    __shared__ unsigned s_mask[RB][4];
    __shared__ int   s_cnt[RB];
    __shared__ int   s_upd[RB];
    __shared__ int   s_idx[RB];
    __shared__ float s_msum[RB];
    __shared__ int   s_mflag[RB];
    __shared__ float s_bd;

    const int tid = threadIdx.x;
    const int row_base = blockIdx.x * RB;

    // ---- load weights + biases into smem ----
    {
        auto cpy = [&](int off, const float* src, int n) {
            for (int i = tid; i < n; i += NTHR) sm[off + i] = src[i];
        };
        cpy(S_WU1, Wu1, GII*64); cpy(S_WR1, Wr1, GII*64); cpy(S_WN1, Wn1, GII*64);
        cpy(S_WO1, Wo1, 64*64);  cpy(S_WU2, Wu2, 64*64);  cpy(S_WR2, Wr2, 64*64);
        cpy(S_WN2, Wn2, 64*64);  cpy(S_WO2, Wo2, 64*64);
        cpy(S_WD, Wd, 64);
        cpy(S_BU1, bu1, 64); cpy(S_BU2, bu2, 64);
        cpy(S_BR1, br1, 64); cpy(S_BR2, br2, 64);
        cpy(S_BN1, bn1, 64); cpy(S_BN2, bn2, 64);
        cpy(S_BO1, bo1, 64); cpy(S_BO2, bo2, 64);
    }
    if (tid == 0) s_bd = bd[0];

    // ---- presence bitmask per row ----
    if (tid < RB) {
        unsigned m0 = 0, m1 = 0, m2 = 0, m3 = 0;
        const int* tp = tsteps + (size_t)(row_base + tid) * TT;
        for (int t = 0; t < TT; ++t) {
            int v = tp[t];           // in [0, 128)
            unsigned bit = 1u << (v & 31);
            int w = v >> 5;
            if (w == 0) m0 |= bit; else if (w == 1) m1 |= bit;
            else if (w == 2) m2 |= bit; else m3 |= bit;
        }
        s_mask[tid][0] = m0; s_mask[tid][1] = m1;
        s_mask[tid][2] = m2; s_mask[tid][3] = m3;
        s_cnt[tid] = 0;
    }
    // initial state y = 0
    for (int e = tid; e < 64 * RB; e += NTHR) sm[S_Y + e] = 0.f;
    __syncthreads();

    const int r0 = 2 * (tid & 15);
    const int c0 = 4 * (tid >> 4);
    float acc[4][2];

    for (int k = 0; k < KK; ++k) {
        // ---- stage 0: per-row scalars ----
        if (tid < RB) {
            int upd = (s_mask[tid][k >> 5] >> (k & 31)) & 1;
            s_upd[tid] = upd;
            s_idx[tid] = s_cnt[tid];
            s_cnt[tid] += upd;
            s_msum[tid] = 0.f;
        }
        __syncthreads();

        // ---- vol partials (from prev_y) ----
        {
            int r = tid & 31, seg = tid >> 5;
            float p = 0.f;
#pragma unroll
            for (int i = 0; i < 8; ++i) {
                int ii = seg * 8 + i;
                p = fmaf(sm[S_Y + ii * RB + r], sm[S_WD + ii], p);
            }
            sm[S_PV + seg * 32 + r] = p;
        }
        // ---- feat gather into YC[64..113], mask-sum ----
        for (int e = tid; e < RB * DD; e += NTHR) {
            int r = e / DD, f = e - r * DD;
            float v = 0.f;
            int idx = s_idx[r];
            if (s_upd[r] && idx < TT)
                v = data[((size_t)(row_base + r) * TT + idx) * DD + f];
            if (f < FF) sm[S_YC + (64 + f) * RB + r] = v;
            else if (v != 0.f) atomicAdd(&s_msum[r], v);
        }
        __syncthreads();

        if (tid < RB) {
            float v = s_bd;
#pragma unroll
            for (int seg = 0; seg < 8; ++seg) v += sm[S_PV + seg * 32 + tid];
            g_vol[(size_t)(row_base + tid) * KK + k] = v;
            s_mflag[tid] = (s_upd[tid] && s_msum[tid] > 0.f) ? 1 : 0;
        }

        // ---- G_o1: H = tanh(Y @ Wo1 + bo1) ----
        mm8<64>(sm + S_Y, sm + S_WO1, r0, c0, acc);
#pragma unroll
        for (int c = 0; c < 4; ++c) {
            int j = c0 + c; float b = sm[S_BO1 + j];
            sm[S_H + j * RB + r0]     = tanhf(acc[c][0] + b);
            sm[S_H + j * RB + r0 + 1] = tanhf(acc[c][1] + b);
        }
        __syncthreads();

        // ---- G_o2: Y1 = H @ Wo2 + bo2 + Y ; YC[0..63] = Y1 ----
        mm8<NUU>(sm + S_H, sm + S_WO2, r0, c0, acc);
#pragma unroll
        for (int c = 0; c < 4; ++c) {
            int j = c0 + c; float b = sm[S_BO2 + j];
            float y0 = sm[S_Y + j * RB + r0];
            float y1 = sm[S_Y + j * RB + r0 + 1];
            float a0 = acc[c][0] + b + y0;
            float a1 = acc[c][1] + b + y1;
            sm[S_Y1 + j * RB + r0]     = a0;
            sm[S_Y1 + j * RB + r0 + 1] = a1;
            sm[S_YC + j * RB + r0]     = a0;
            sm[S_YC + j * RB + r0 + 1] = a1;
        }
        __syncthreads();

        // ---- G_u1: H = tanh(YC @ Wu1 + bu1) ----
        mm8<GII>(sm + S_YC, sm + S_WU1, r0, c0, acc);
#pragma unroll
        for (int c = 0; c < 4; ++c) {
            int j = c0 + c; float b = sm[S_BU1 + j];
            sm[S_H + j * RB + r0]     = tanhf(acc[c][0] + b);
            sm[S_H + j * RB + r0 + 1] = tanhf(acc[c][1] + b);
        }
        __syncthreads();

        // ---- G_u2: U = sigmoid(H @ Wu2 + bu2) ----
        mm8<NUU>(sm + S_H, sm + S_WU2, r0, c0, acc);
#pragma unroll
        for (int c = 0; c < 4; ++c) {
            int j = c0 + c; float b = sm[S_BU2 + j];
            sm[S_U + j * RB + r0]     = sigm(acc[c][0] + b);
            sm[S_U + j * RB + r0 + 1] = sigm(acc[c][1] + b);
        }
        __syncthreads();

        // ---- G_r1: H = tanh(YC @ Wr1 + br1) ----
        mm8<GII>(sm + S_YC, sm + S_WR1, r0, c0, acc);
#pragma unroll
        for (int c = 0; c < 4; ++c) {
            int j = c0 + c; float b = sm[S_BR1 + j];
            sm[S_H + j * RB + r0]     = tanhf(acc[c][0] + b);
            sm[S_H + j * RB + r0 + 1] = tanhf(acc[c][1] + b);
        }
        __syncthreads();

        // ---- G_r2: r = sigmoid(H @ Wr2 + br2); YC[0..63] = Y1 * r ----
        mm8<NUU>(sm + S_H, sm + S_WR2, r0, c0, acc);
#pragma unroll
        for (int c = 0; c < 4; ++c) {
            int j = c0 + c; float b = sm[S_BR2 + j];
            float rg0 = sigm(acc[c][0] + b);
            float rg1 = sigm(acc[c][1] + b);
            sm[S_YC + j * RB + r0]     = sm[S_Y1 + j * RB + r0]     * rg0;
            sm[S_YC + j * RB + r0 + 1] = sm[S_Y1 + j * RB + r0 + 1] * rg1;
        }
        __syncthreads();

        // ---- G_n1: H = tanh(YC @ Wn1 + bn1) ----
        mm8<GII>(sm + S_YC, sm + S_WN1, r0, c0, acc);
#pragma unroll
        for (int c = 0; c < 4; ++c) {
            int j = c0 + c; float b = sm[S_BN1 + j];
            sm[S_H + j * RB + r0]     = tanhf(acc[c][0] + b);
            sm[S_H + j * RB + r0 + 1] = tanhf(acc[c][1] + b);
        }
        __syncthreads();

        // ---- G_n2: ns = H @ Wn2 + bn2 ; blend ; write new Y ----
        mm8<NUU>(sm + S_H, sm + S_WN2, r0, c0, acc);
        {
            int m0 = s_mflag[r0], m1 = s_mflag[r0 + 1];
#pragma unroll
            for (int c = 0; c < 4; ++c) {
                int j = c0 + c; float b = sm[S_BN2 + j];
                float ns0 = acc[c][0] + b;
                float ns1 = acc[c][1] + b;
                float u0 = sm[S_U + j * RB + r0];
                float u1 = sm[S_U + j * RB + r0 + 1];
                float y10 = sm[S_Y1 + j * RB + r0];
                float y11 = sm[S_Y1 + j * RB + r0 + 1];
                float ny0 = fmaf(1.f - u0, ns0, u0 * y10);
                float ny1 = fmaf(1.f - u1, ns1, u1 * y11);
                // (upd && m) selects ny, else y1 (exact binary select == ref blend)
                sm[S_Y + j * RB + r0]     = m0 ? ny0 : y10;
                sm[S_Y + j * RB + r0 + 1] = m1 ? ny1 : y11;
            }
        }
        __syncthreads();
    }

    // ---- write final prev_y ----
    for (int e = tid; e < 64 * RB; e += NTHR) {
        int j = e >> 5, r = e & 31;
        out_prevy[(size_t)(row_base + r) * 64 + j] = sm[S_Y + j * RB + r];
    }
}

__global__ void lobrm_gather(const int* __restrict__ tsteps,
                             float* __restrict__ out_sel,
                             float* __restrict__ out_ti)
{
    int i = blockIdx.x * blockDim.x + threadIdx.x;
    if (i >= BB * (TT - 1)) return;
    int b = i / (TT - 1);
    int t = i - b * (TT - 1);
    int v0 = tsteps[(size_t)b * TT + t];
    int v1 = tsteps[(size_t)b * TT + t + 1];
    int inv = v0 < 0 ? 0 : (v0 > KK - 2 ? KK - 2 : v0);
    out_sel[i] = g_vol[(size_t)b * KK + inv + 1];
    out_ti[i]  = (float)(v1 - v0);
}

extern "C" void kernel_launch(void* const* d_in, const int* in_sizes, int n_in,
                              void* d_out, int out_size) {
    const float* data = (const float*)d_in[0];
    const int*   ts   = (const int*)d_in[1];
    const float* Wu1 = (const float*)d_in[2];
    const float* bu1 = (const float*)d_in[3];
    const float* Wu2 = (const float*)d_in[4];
    const float* bu2 = (const float*)d_in[5];
    const float* Wr1 = (const float*)d_in[6];
    const float* br1 = (const float*)d_in[7];
    const float* Wr2 = (const float*)d_in[8];
    const float* br2 = (const float*)d_in[9];
    const float* Wn1 = (const float*)d_in[10];
    const float* bn1 = (const float*)d_in[11];
    const float* Wn2 = (const float*)d_in[12];
    const float* bn2 = (const float*)d_in[13];
    const float* Wo1 = (const float*)d_in[14];
    const float* bo1 = (const float*)d_in[15];
    const float* Wo2 = (const float*)d_in[16];
    const float* bo2 = (const float*)d_in[17];
    const float* Wd  = (const float*)d_in[18];
    const float* bd  = (const float*)d_in[19];

    float* out = (float*)d_out;
    float* out_prevy = out;                       // B*64
    float* out_sel   = out + (size_t)BB * LL;     // B*63
    float* out_ti    = out_sel + (size_t)BB * (TT - 1);

    cudaFuncSetAttribute(lobrm_main, cudaFuncAttributeMaxDynamicSharedMemorySize,
                         SMEM_BYTES);
    lobrm_main<<<BB / RB, NTHR, SMEM_BYTES>>>(
        data, ts, Wu1, bu1, Wu2, bu2, Wr1, br1, Wr2, br2,
        Wn1, bn1, Wn2, bn2, Wo1, bo1, Wo2, bo2, Wd, bd, out_prevy);
    lobrm_gather<<<(BB * (TT - 1) + 255) / 256, 256>>>(ts, out_sel, out_ti);
}

// round 3
// speedup vs baseline: 1.4233x; 1.4233x over previous
#include <cuda_runtime.h>
#include <math.h>

// Problem constants
#define BB   4096
#define TT   64
#define DD   100
#define FF   50
#define LL   64
#define NUU  64
#define KK   128
#define GII  114   // F + L
#define RB   32    // rows per CTA
#define NTHR 256

// ---- dynamic shared memory layout (floats) ----
#define S_WU1 0
#define S_WR1 (S_WU1 + GII*64)
#define S_WN1 (S_WR1 + GII*64)
#define S_WO1 (S_WN1 + GII*64)
#define S_WU2 (S_WO1 + 64*64)
#define S_WR2 (S_WU2 + 64*64)
#define S_WN2 (S_WR2 + 64*64)
#define S_WO2 (S_WN2 + 64*64)
#define S_WD  (S_WO2 + 64*64)
#define S_BU1 (S_WD + 64)
#define S_BU2 (S_BU1 + 64)
#define S_BR1 (S_BU2 + 64)
#define S_BR2 (S_BR1 + 64)
#define S_BN1 (S_BR2 + 64)
#define S_BN2 (S_BN1 + 64)
#define S_BO1 (S_BN2 + 64)
#define S_BO2 (S_BO1 + 64)
#define S_Y   (S_BO2 + 64)
#define S_Y1  (S_Y  + 64*RB)
#define S_H   (S_Y1 + 64*RB)
#define S_U   (S_H  + 64*RB)
#define S_YC  (S_U  + 64*RB)          // 114 x 32
#define S_PV  (S_YC + GII*RB)         // 8 x 32 vol partials
#define S_END (S_PV + 8*32)
#define SMEM_BYTES (S_END * 4)        // 220160 bytes

// scratch: per-row per-step volume output
__device__ float g_vol[BB * KK];

// fast activations via MUFU ex2 (rel err ~1e-6; exact saturation at +/-1)
__device__ __forceinline__ float fast_sigm(float x) {
    return __fdividef(1.0f, 1.0f + __expf(-x));
}
__device__ __forceinline__ float fast_tanh(float x) {
    return fmaf(2.0f, __fdividef(1.0f, 1.0f + __expf(-2.0f * x)), -1.0f);
}

// All-row GEMM: C[32r x 64c] = A[KI x 32] * W[KI x 64]; thread = 2 rows x 4 cols.
template<int KI>
__device__ __forceinline__ void mm8(const float* __restrict__ A,
                                    const float* __restrict__ W,
                                    int r0, int c0, float (&acc)[4][2]) {
#pragma unroll
    for (int c = 0; c < 4; ++c) { acc[c][0] = 0.f; acc[c][1] = 0.f; }
#pragma unroll 2
    for (int i = 0; i < KI; ++i) {
        float2 a = *reinterpret_cast<const float2*>(A + i * RB + r0);
        float4 w = *reinterpret_cast<const float4*>(W + i * 64 + c0);
        acc[0][0] = fmaf(a.x, w.x, acc[0][0]);
        acc[0][1] = fmaf(a.y, w.x, acc[0][1]);
        acc[1][0] = fmaf(a.x, w.y, acc[1][0]);
        acc[1][1] = fmaf(a.y, w.y, acc[1][1]);
        acc[2][0] = fmaf(a.x, w.z, acc[2][0]);
        acc[2][1] = fmaf(a.y, w.z, acc[2][1]);
        acc[3][0] = fmaf(a.x, w.w, acc[3][0]);
        acc[3][1] = fmaf(a.y, w.w, acc[3][1]);
    }
}

// Compacted GEMM: rows gathered via ra0/ra1 (uniform per half-warp -> broadcast LDS)
template<int KI>
__device__ __forceinline__ void mmc(const float* __restrict__ A,
                                    const float* __restrict__ W,
                                    int ra0, int ra1, int c0, float (&acc)[4][2]) {
#pragma unroll
    for (int c = 0; c < 4; ++c) { acc[c][0] = 0.f; acc[c][1] = 0.f; }
#pragma unroll 2
    for (int i = 0; i < KI; ++i) {
        float a0 = A[i * RB + ra0];
        float a1 = A[i * RB + ra1];
        float4 w = *reinterpret_cast<const float4*>(W + i * 64 + c0);
        acc[0][0] = fmaf(a0, w.x, acc[0][0]);
        acc[0][1] = fmaf(a1, w.x, acc[0][1]);
        acc[1][0] = fmaf(a0, w.y, acc[1][0]);
        acc[1][1] = fmaf(a1, w.y, acc[1][1]);
        acc[2][0] = fmaf(a0, w.z, acc[2][0]);
        acc[2][1] = fmaf(a1, w.z, acc[2][1]);
        acc[3][0] = fmaf(a0, w.w, acc[3][0]);
        acc[3][1] = fmaf(a1, w.w, acc[3][1]);
    }
}

__global__ void __launch_bounds__(NTHR, 1) lobrm_main(
    const float* __restrict__ data, const int* __restrict__ tsteps,
    const float* __restrict__ Wu1, const float* __restrict__ bu1,
    const float* __restrict__ Wu2, const float* __restrict__ bu2,
    const float* __restrict__ Wr1, const float* __restrict__ br1,
    const float* __restrict__ Wr2, const float* __restrict__ br2,
    const float* __restrict__ Wn1, const float* __restrict__ bn1,
    const float* __restrict__ Wn2, const float* __restrict__ bn2,
    const float* __restrict__ Wo1, const float* __restrict__ bo1,
    const float* __restrict__ Wo2, const float* __restrict__ bo2,
    const float* __restrict__ Wd,  const float* __restrict__ bd,
    float* __restrict__ out_prevy)
{
    extern __shared__ float sm[];
    __shared__ unsigned char s_act[KK][RB];   // active rows per step (compacted)
    __shared__ unsigned char s_idxk[KK][RB];  // event index per (step, row)
    __shared__ int   s_nact[KK];
    __shared__ int   s_morflag[RB];           // any-mask-nonzero flag (benign race)
    __shared__ int   s_mflag[RB];
    __shared__ float s_bd;

    const int tid = threadIdx.x;
    const int row_base = blockIdx.x * RB;

    // ---- load weights + biases into smem ----
    {
        auto cpy = [&](int off, const float* src, int n) {
            for (int i = tid; i < n; i += NTHR) sm[off + i] = src[i];
        };
        cpy(S_WU1, Wu1, GII*64); cpy(S_WR1, Wr1, GII*64); cpy(S_WN1, Wn1, GII*64);
        cpy(S_WO1, Wo1, 64*64);  cpy(S_WU2, Wu2, 64*64);  cpy(S_WR2, Wr2, 64*64);
        cpy(S_WN2, Wn2, 64*64);  cpy(S_WO2, Wo2, 64*64);
        cpy(S_WD, Wd, 64);
        cpy(S_BU1, bu1, 64); cpy(S_BU2, bu2, 64);
        cpy(S_BR1, br1, 64); cpy(S_BR2, br2, 64);
        cpy(S_BN1, bn1, 64); cpy(S_BN2, bn2, 64);
        cpy(S_BO1, bo1, 64); cpy(S_BO2, bo2, 64);
    }
    if (tid == 0) s_bd = bd[0];

    // ---- warp 0: build presence masks, per-step active lists + event indices ----
    if (tid < RB) {
        const int r = tid;
        unsigned m0 = 0, m1 = 0, m2 = 0, m3 = 0;
        const int* tp = tsteps + (size_t)(row_base + r) * TT;
        for (int t = 0; t < TT; ++t) {
            int v = tp[t];           // in [0, 128)
            unsigned bit = 1u << (v & 31);
            int w = v >> 5;
            if (w == 0) m0 |= bit; else if (w == 1) m1 |= bit;
            else if (w == 2) m2 |= bit; else m3 |= bit;
        }
        const unsigned below = (r == 31) ? 0x7fffffffu : ((1u << r) - 1u);
        int c = 0;
        for (int k = 0; k < KK; ++k) {
            unsigned mk = (k < 32) ? m0 : (k < 64) ? m1 : (k < 96) ? m2 : m3;
            int bit = (mk >> (k & 31)) & 1;
            unsigned bal = __ballot_sync(0xffffffffu, bit);
            if (r == 0) s_nact[k] = __popc(bal);
            s_idxk[k][r] = (unsigned char)c;
            if (bit) s_act[k][__popc(bal & below)] = (unsigned char)r;
            c += bit;
        }
        s_morflag[r] = 0;
    }
    // initial state y = 0
    for (int e = tid; e < 64 * RB; e += NTHR) sm[S_Y + e] = 0.f;
    __syncthreads();

    // all-row mapping
    const int r0 = 2 * (tid & 15);
    const int c0 = 4 * (tid >> 4);
    // compacted mapping: warp owns 2 row-pairs, 16 lanes cover 64 cols
    const int cw    = tid >> 5;
    const int cpair = 2 * cw + ((tid >> 4) & 1);
    const int cc0   = 4 * (tid & 15);
    float acc[4][2];

    for (int k = 0; k < KK; ++k) {
        const int nact = s_nact[k];
        const unsigned char* actk = s_act[k];

        // ================= P1: feat prefetch + vol partial + o1 =================
        const int nel = nact * DD;
        float fv[13];
#pragma unroll
        for (int it = 0; it < 13; ++it) {
            int e = tid + it * NTHR;
            fv[it] = 0.f;
            if (e < nel) {
                int q = e / DD, f = e - q * DD;
                int ra = actk[q];
                int idx = s_idxk[k][ra];
                fv[it] = data[((size_t)(row_base + ra) * TT + idx) * DD + f];
            }
        }
        // vol partials from prev_y
        {
            int rr = tid & 31, seg = tid >> 5;
            float p = 0.f;
#pragma unroll
            for (int i = 0; i < 8; ++i) {
                int ii = seg * 8 + i;
                p = fmaf(sm[S_Y + ii * RB + rr], sm[S_WD + ii], p);
            }
            sm[S_PV + seg * 32 + rr] = p;
        }
        // o1: H = tanh(Y @ Wo1 + bo1)
        mm8<64>(sm + S_Y, sm + S_WO1, r0, c0, acc);
#pragma unroll
        for (int c = 0; c < 4; ++c) {
            int j = c0 + c; float b = sm[S_BO1 + j];
            sm[S_H + j * RB + r0]     = fast_tanh(acc[c][0] + b);
            sm[S_H + j * RB + r0 + 1] = fast_tanh(acc[c][1] + b);
        }
        // store fetched feat + mask flags
#pragma unroll
        for (int it = 0; it < 13; ++it) {
            int e = tid + it * NTHR;
            if (e < nel) {
                int q = e / DD, f = e - q * DD;
                int ra = actk[q];
                if (f < FF) sm[S_YC + (64 + f) * RB + ra] = fv[it];
                else if (fv[it] != 0.f) s_morflag[ra] = 1;   // benign race
            }
        }
        __syncthreads();

        // ================= P2: o2 (y1 for ALL rows) + vol finalize =================
        mm8<NUU>(sm + S_H, sm + S_WO2, r0, c0, acc);
#pragma unroll
        for (int c = 0; c < 4; ++c) {
            int j = c0 + c; float b = sm[S_BO2 + j];
            float y0 = sm[S_Y + j * RB + r0];
            float y1 = sm[S_Y + j * RB + r0 + 1];
            float a0 = acc[c][0] + b + y0;
            float a1 = acc[c][1] + b + y1;
            sm[S_Y  + j * RB + r0]     = a0;   // default next state = y1
            sm[S_Y  + j * RB + r0 + 1] = a1;
            sm[S_Y1 + j * RB + r0]     = a0;
            sm[S_Y1 + j * RB + r0 + 1] = a1;
            sm[S_YC + j * RB + r0]     = a0;
            sm[S_YC + j * RB + r0 + 1] = a1;
        }
        if (tid < RB) {
            float v = s_bd;
#pragma unroll
            for (int seg = 0; seg < 8; ++seg) v += sm[S_PV + seg * 32 + tid];
            g_vol[(size_t)(row_base + tid) * KK + k] = v;
            s_mflag[tid] = s_morflag[tid];
            s_morflag[tid] = 0;
        }
        __syncthreads();

        // compacted row assignment for this step
        const int s0 = 2 * cpair, s1 = s0 + 1;
        const bool v0 = s0 < nact, v1 = s1 < nact;
        const int ra0 = actk[v0 ? s0 : 0];
        const int ra1 = actk[v1 ? s1 : 0];
        const bool wact = (4 * cw) < nact;   // warp-uniform

        // ================= P3: u1 =================
        if (wact) {
            mmc<GII>(sm + S_YC, sm + S_WU1, ra0, ra1, cc0, acc);
#pragma unroll
            for (int c = 0; c < 4; ++c) {
                int j = cc0 + c; float b = sm[S_BU1 + j];
                if (v0) sm[S_H + j * RB + ra0] = fast_tanh(acc[c][0] + b);
                if (v1) sm[S_H + j * RB + ra1] = fast_tanh(acc[c][1] + b);
            }
        }
        __syncthreads();
        // ================= P4: u2 =================
        if (wact) {
            mmc<NUU>(sm + S_H, sm + S_WU2, ra0, ra1, cc0, acc);
#pragma unroll
            for (int c = 0; c < 4; ++c) {
                int j = cc0 + c; float b = sm[S_BU2 + j];
                if (v0) sm[S_U + j * RB + ra0] = fast_sigm(acc[c][0] + b);
                if (v1) sm[S_U + j * RB + ra1] = fast_sigm(acc[c][1] + b);
            }
        }
        __syncthreads();
        // ================= P5: r1 =================
        if (wact) {
            mmc<GII>(sm + S_YC, sm + S_WR1, ra0, ra1, cc0, acc);
#pragma unroll
            for (int c = 0; c < 4; ++c) {
                int j = cc0 + c; float b = sm[S_BR1 + j];
                if (v0) sm[S_H + j * RB + ra0] = fast_tanh(acc[c][0] + b);
                if (v1) sm[S_H + j * RB + ra1] = fast_tanh(acc[c][1] + b);
            }
        }
        __syncthreads();
        // ================= P6: r2 -> YC[0:64] = y1 * r =================
        if (wact) {
            mmc<NUU>(sm + S_H, sm + S_WR2, ra0, ra1, cc0, acc);
#pragma unroll
            for (int c = 0; c < 4; ++c) {
                int j = cc0 + c; float b = sm[S_BR2 + j];
                float rg0 = fast_sigm(acc[c][0] + b);
                float rg1 = fast_sigm(acc[c][1] + b);
                if (v0) sm[S_YC + j * RB + ra0] = sm[S_Y1 + j * RB + ra0] * rg0;
                if (v1) sm[S_YC + j * RB + ra1] = sm[S_Y1 + j * RB + ra1] * rg1;
            }
        }
        __syncthreads();
        // ================= P7: n1 =================
        if (wact) {
            mmc<GII>(sm + S_YC, sm + S_WN1, ra0, ra1, cc0, acc);
#pragma unroll
            for (int c = 0; c < 4; ++c) {
                int j = cc0 + c; float b = sm[S_BN1 + j];
                if (v0) sm[S_H + j * RB + ra0] = fast_tanh(acc[c][0] + b);
                if (v1) sm[S_H + j * RB + ra1] = fast_tanh(acc[c][1] + b);
            }
        }
        __syncthreads();
        // ================= P8: n2 + blend (active rows only) =================
        if (wact) {
            mmc<NUU>(sm + S_H, sm + S_WN2, ra0, ra1, cc0, acc);
            const int m0f = s_mflag[ra0];
            const int m1f = s_mflag[ra1];
#pragma unroll
            for (int c = 0; c < 4; ++c) {
                int j = cc0 + c; float b = sm[S_BN2 + j];
                float ns0 = acc[c][0] + b;
                float ns1 = acc[c][1] + b;
                float u0  = sm[S_U  + j * RB + ra0];
                float u1  = sm[S_U  + j * RB + ra1];
                float y10 = sm[S_Y1 + j * RB + ra0];
                float y11 = sm[S_Y1 + j * RB + ra1];
                float ny0 = fmaf(1.f - u0, ns0, u0 * y10);
                float ny1 = fmaf(1.f - u1, ns1, u1 * y11);
                if (v0) sm[S_Y + j * RB + ra0] = m0f ? ny0 : y10;
                if (v1) sm[S_Y + j * RB + ra1] = m1f ? ny1 : y11;
            }
        }
        __syncthreads();
    }

    // ---- write final prev_y ----
    for (int e = tid; e < 64 * RB; e += NTHR) {
        int j = e >> 5, r = e & 31;
        out_prevy[(size_t)(row_base + r) * 64 + j] = sm[S_Y + j * RB + r];
    }
}

__global__ void lobrm_gather(const int* __restrict__ tsteps,
                             float* __restrict__ out_sel,
                             float* __restrict__ out_ti)
{
    int i = blockIdx.x * blockDim.x + threadIdx.x;
    if (i >= BB * (TT - 1)) return;
    int b = i / (TT - 1);
    int t = i - b * (TT - 1);
    int v0 = tsteps[(size_t)b * TT + t];
    int v1 = tsteps[(size_t)b * TT + t + 1];
    int inv = v0 < 0 ? 0 : (v0 > KK - 2 ? KK - 2 : v0);
    out_sel[i] = g_vol[(size_t)b * KK + inv + 1];
    out_ti[i]  = (float)(v1 - v0);
}

extern "C" void kernel_launch(void* const* d_in, const int* in_sizes, int n_in,
                              void* d_out, int out_size) {
    const float* data = (const float*)d_in[0];
    const int*   ts   = (const int*)d_in[1];
    const float* Wu1 = (const float*)d_in[2];
    const float* bu1 = (const float*)d_in[3];
    const float* Wu2 = (const float*)d_in[4];
    const float* bu2 = (const float*)d_in[5];
    const float* Wr1 = (const float*)d_in[6];
    const float* br1 = (const float*)d_in[7];
    const float* Wr2 = (const float*)d_in[8];
    const float* br2 = (const float*)d_in[9];
    const float* Wn1 = (const float*)d_in[10];
    const float* bn1 = (const float*)d_in[11];
    const float* Wn2 = (const float*)d_in[12];
    const float* bn2 = (const float*)d_in[13];
    const float* Wo1 = (const float*)d_in[14];
    const float* bo1 = (const float*)d_in[15];
    const float* Wo2 = (const float*)d_in[16];
    const float* bo2 = (const float*)d_in[17];
    const float* Wd  = (const float*)d_in[18];
    const float* bd  = (const float*)d_in[19];

    float* out = (float*)d_out;
    float* out_prevy = out;                       // B*64
    float* out_sel   = out + (size_t)BB * LL;     // B*63
    float* out_ti    = out_sel + (size_t)BB * (TT - 1);

    cudaFuncSetAttribute(lobrm_main, cudaFuncAttributeMaxDynamicSharedMemorySize,
                         SMEM_BYTES);
    lobrm_main<<<BB / RB, NTHR, SMEM_BYTES>>>(
        data, ts, Wu1, bu1, Wu2, bu2, Wr1, br1, Wr2, br2,
        Wn1, bn1, Wn2, bn2, Wo1, bo1, Wo2, bo2, Wd, bd, out_prevy);
    lobrm_gather<<<(BB * (TT - 1) + 255) / 256, 256>>>(ts, out_sel, out_ti);
}

// round 4
// speedup vs baseline: 1.4672x; 1.0309x over previous
#include <cuda_runtime.h>
#include <math.h>

// Problem constants
#define BB   4096
#define TT   64
#define DD   100
#define FF   50
#define LL   64
#define NUU  64
#define KK   128
#define GII  114   // F + L
#define RB   32    // rows per CTA
#define NTHR 256
#define SP   33    // padded row stride for activation buffers (bank-conflict free)

// ---- dynamic shared memory layout (floats) ----
#define S_WU1 0
#define S_WR1 (S_WU1 + GII*64)
#define S_WN1 (S_WR1 + GII*64)
#define S_WO1 (S_WN1 + GII*64)
#define S_WU2 (S_WO1 + 64*64)
#define S_WR2 (S_WU2 + 64*64)
#define S_WN2 (S_WR2 + 64*64)
#define S_WO2 (S_WN2 + 64*64)
#define S_WD  (S_WO2 + 64*64)
#define S_BU1 (S_WD + 64)
#define S_BU2 (S_BU1 + 64)
#define S_BR1 (S_BU2 + 64)
#define S_BR2 (S_BR1 + 64)
#define S_BN1 (S_BR2 + 64)
#define S_BN2 (S_BN1 + 64)
#define S_BO1 (S_BN2 + 64)
#define S_BO2 (S_BO1 + 64)
#define S_Y   (S_BO2 + 64)
#define S_H   (S_Y  + 64*SP)
#define S_U   (S_H  + 64*SP)
#define S_YC  (S_U  + 64*SP)          // 114 x SP
#define S_PV  (S_YC + GII*SP)         // 8 x 32 vol partials
#define S_END (S_PV + 8*32)
#define SMEM_BYTES (S_END * 4)        // ~213 KB

typedef unsigned long long u64;

// scratch: per-row per-step volume output
__device__ float g_vol[BB * KK];

// ---- fast math primitives ----
__device__ __forceinline__ float fast_rcp(float x) {
    float r; asm("rcp.approx.f32 %0, %1;" : "=f"(r) : "f"(x)); return r;
}
__device__ __forceinline__ float fast_ex2(float x) {
    float r; asm("ex2.approx.f32 %0, %1;" : "=f"(r) : "f"(x)); return r;
}
__device__ __forceinline__ float fast_sigm(float x) {
    return fast_rcp(1.0f + fast_ex2(-1.4426950408889634f * x));
}
__device__ __forceinline__ float fast_tanh(float x) {
    return fmaf(2.0f, fast_rcp(1.0f + fast_ex2(-2.8853900817779268f * x)), -1.0f);
}

// ---- packed f32x2 primitives ----
__device__ __forceinline__ u64 pack2(float x) {
    u64 r; asm("mov.b64 %0, {%1, %1};" : "=l"(r) : "f"(x)); return r;
}
__device__ __forceinline__ void fma2(u64& d, u64 a, u64 b) {
    asm("fma.rn.f32x2 %0, %1, %2, %0;" : "+l"(d) : "l"(a), "l"(b));
}
__device__ __forceinline__ float2 unpack2(u64 v) {
    float2 f; asm("mov.b64 {%0, %1}, %2;" : "=f"(f.x), "=f"(f.y) : "l"(v)); return f;
}

// All-row GEMM: thread = row r (lane), cols [c0, c0+8); A stride SP, W stride 64.
template<int KI>
__device__ __forceinline__ void mmA(const float* __restrict__ A,
                                    const float* __restrict__ W,
                                    int r, int c0, u64 (&acc)[4]) {
    acc[0] = acc[1] = acc[2] = acc[3] = 0ULL;
#pragma unroll 2
    for (int i = 0; i < KI; ++i) {
        u64 aa = pack2(A[i * SP + r]);
        ulonglong2 w0 = *reinterpret_cast<const ulonglong2*>(W + i * 64 + c0);
        ulonglong2 w1 = *reinterpret_cast<const ulonglong2*>(W + i * 64 + c0 + 4);
        fma2(acc[0], aa, w0.x);
        fma2(acc[1], aa, w0.y);
        fma2(acc[2], aa, w1.x);
        fma2(acc[3], aa, w1.y);
    }
}

// Compacted GEMM: thread = gathered row ra, cols [cb, cb+4).
template<int KI>
__device__ __forceinline__ void mmC(const float* __restrict__ A,
                                    const float* __restrict__ W,
                                    int ra, int cb, u64 (&acc)[2]) {
    acc[0] = acc[1] = 0ULL;
#pragma unroll 2
    for (int i = 0; i < KI; ++i) {
        u64 aa = pack2(A[i * SP + ra]);
        ulonglong2 w = *reinterpret_cast<const ulonglong2*>(W + i * 64 + cb);
        fma2(acc[0], aa, w.x);
        fma2(acc[1], aa, w.y);
    }
}

#define PAIR_BAR(grp) asm volatile("bar.sync %0, 64;" :: "r"(1 + (grp)) : "memory")

__global__ void __launch_bounds__(NTHR, 1) lobrm_main(
    const float* __restrict__ data, const int* __restrict__ tsteps,
    const float* __restrict__ Wu1, const float* __restrict__ bu1,
    const float* __restrict__ Wu2, const float* __restrict__ bu2,
    const float* __restrict__ Wr1, const float* __restrict__ br1,
    const float* __restrict__ Wr2, const float* __restrict__ br2,
    const float* __restrict__ Wn1, const float* __restrict__ bn1,
    const float* __restrict__ Wn2, const float* __restrict__ bn2,
    const float* __restrict__ Wo1, const float* __restrict__ bo1,
    const float* __restrict__ Wo2, const float* __restrict__ bo2,
    const float* __restrict__ Wd,  const float* __restrict__ bd,
    float* __restrict__ out_prevy)
{
    extern __shared__ float sm[];
    __shared__ unsigned char s_act[KK][RB];   // active rows per step (compacted)
    __shared__ unsigned char s_idxk[KK][RB];  // event index per (step, row)
    __shared__ int   s_nact[KK];
    __shared__ int   s_morflag[RB];           // any-mask-nonzero flag (benign race)
    __shared__ int   s_mflag[RB];
    __shared__ float s_bd;

    const int tid = threadIdx.x;
    const int row_base = blockIdx.x * RB;

    // ---- load weights + biases into smem ----
    {
        auto cpy = [&](int off, const float* src, int n) {
            for (int i = tid; i < n; i += NTHR) sm[off + i] = src[i];
        };
        cpy(S_WU1, Wu1, GII*64); cpy(S_WR1, Wr1, GII*64); cpy(S_WN1, Wn1, GII*64);
        cpy(S_WO1, Wo1, 64*64);  cpy(S_WU2, Wu2, 64*64);  cpy(S_WR2, Wr2, 64*64);
        cpy(S_WN2, Wn2, 64*64);  cpy(S_WO2, Wo2, 64*64);
        cpy(S_WD, Wd, 64);
        cpy(S_BU1, bu1, 64); cpy(S_BU2, bu2, 64);
        cpy(S_BR1, br1, 64); cpy(S_BR2, br2, 64);
        cpy(S_BN1, bn1, 64); cpy(S_BN2, bn2, 64);
        cpy(S_BO1, bo1, 64); cpy(S_BO2, bo2, 64);
    }
    if (tid == 0) s_bd = bd[0];

    // ---- warp 0: presence masks, per-step active lists + event indices ----
    if (tid < RB) {
        const int r = tid;
        unsigned m0 = 0, m1 = 0, m2 = 0, m3 = 0;
        const int* tp = tsteps + (size_t)(row_base + r) * TT;
        for (int t = 0; t < TT; ++t) {
            int v = tp[t];           // in [0, 128)
            unsigned bit = 1u << (v & 31);
            int w = v >> 5;
            if (w == 0) m0 |= bit; else if (w == 1) m1 |= bit;
            else if (w == 2) m2 |= bit; else m3 |= bit;
        }
        const unsigned below = (r == 31) ? 0x7fffffffu : ((1u << r) - 1u);
        int c = 0;
        for (int k = 0; k < KK; ++k) {
            unsigned mk = (k < 32) ? m0 : (k < 64) ? m1 : (k < 96) ? m2 : m3;
            int bit = (mk >> (k & 31)) & 1;
            unsigned bal = __ballot_sync(0xffffffffu, bit);
            if (r == 0) s_nact[k] = __popc(bal);
            s_idxk[k][r] = (unsigned char)c;
            if (bit) s_act[k][__popc(bal & below)] = (unsigned char)r;
            c += bit;
        }
        s_morflag[r] = 0;
    }
    // initial state y = 0 (pads included, harmless)
    for (int e = tid; e < 64 * SP; e += NTHR) sm[S_Y + e] = 0.f;
    __syncthreads();

    // all-row mapping: thread = row (lane), 8 cols per warp slice
    const int lane = tid & 31;
    const int wid  = tid >> 5;
    const int rA   = lane;
    const int c0   = 8 * wid;
    // compacted mapping: pair = wid>>1 owns 4 rows; half = wid&1 owns 32 cols
    const int group = wid >> 1;
    const int half  = wid & 1;
    const int p  = lane >> 3;       // row slot within group
    const int g  = lane & 7;        // col group of 4
    const int cb = 32 * half + 4 * g;

    u64 acc4[4];
    u64 acc2[2];

    for (int k = 0; k < KK; ++k) {
        const int nact = s_nact[k];
        const unsigned char* actk = s_act[k];

        // ================= P1: feat prefetch + vol partial + o1 =================
        const int nel = nact * DD;
        float fv[13];
#pragma unroll
        for (int it = 0; it < 13; ++it) {
            int e = tid + it * NTHR;
            fv[it] = 0.f;
            if (e < nel) {
                int q = e / DD, f = e - q * DD;
                int ra = actk[q];
                int idx = s_idxk[k][ra];
                fv[it] = data[((size_t)(row_base + ra) * TT + idx) * DD + f];
            }
        }
        // vol partials from prev_y
        {
            float pv = 0.f;
#pragma unroll
            for (int i = 0; i < 8; ++i) {
                int ii = wid * 8 + i;
                pv = fmaf(sm[S_Y + ii * SP + lane], sm[S_WD + ii], pv);
            }
            sm[S_PV + wid * 32 + lane] = pv;
        }
        // o1: H = tanh(Y @ Wo1 + bo1)
        mmA<64>(sm + S_Y, sm + S_WO1, rA, c0, acc4);
#pragma unroll
        for (int c = 0; c < 4; ++c) {
            float2 v = unpack2(acc4[c]);
            int j = c0 + 2 * c;
            sm[S_H + j * SP + rA]       = fast_tanh(v.x + sm[S_BO1 + j]);
            sm[S_H + (j + 1) * SP + rA] = fast_tanh(v.y + sm[S_BO1 + j + 1]);
        }
        // store fetched feat + mask flags
#pragma unroll
        for (int it = 0; it < 13; ++it) {
            int e = tid + it * NTHR;
            if (e < nel) {
                int q = e / DD, f = e - q * DD;
                int ra = actk[q];
                if (f < FF) sm[S_YC + (64 + f) * SP + ra] = fv[it];
                else if (fv[it] != 0.f) s_morflag[ra] = 1;   // benign race
            }
        }
        __syncthreads();

        // ================= P2: o2 -> y1 for ALL rows + vol finalize =================
        mmA<64>(sm + S_H, sm + S_WO2, rA, c0, acc4);
#pragma unroll
        for (int c = 0; c < 4; ++c) {
            float2 v = unpack2(acc4[c]);
            int j = c0 + 2 * c;
            float a0 = v.x + sm[S_BO2 + j]     + sm[S_Y + j * SP + rA];
            float a1 = v.y + sm[S_BO2 + j + 1] + sm[S_Y + (j + 1) * SP + rA];
            sm[S_Y  + j * SP + rA]       = a0;   // default next state = y1
            sm[S_Y  + (j + 1) * SP + rA] = a1;
            sm[S_YC + j * SP + rA]       = a0;
            sm[S_YC + (j + 1) * SP + rA] = a1;
        }
        if (tid < RB) {
            float v = s_bd;
#pragma unroll
            for (int seg = 0; seg < 8; ++seg) v += sm[S_PV + seg * 32 + tid];
            g_vol[(size_t)(row_base + tid) * KK + k] = v;
            s_mflag[tid] = s_morflag[tid];
            s_morflag[tid] = 0;
        }
        __syncthreads();

        // ================= fused compacted u/r/n chain =================
        for (int base = 0; base < nact; base += 16) {
            const int slot = base + 4 * group + p;
            const bool valid = slot < nact;
            const int ra = actk[slot & 31] & 31;
            const bool wact = (base + 4 * group) < nact;   // pair-uniform
            if (wact) {
                // u1
                mmC<GII>(sm + S_YC, sm + S_WU1, ra, cb, acc2);
#pragma unroll
                for (int c = 0; c < 2; ++c) {
                    float2 v = unpack2(acc2[c]);
                    int j = cb + 2 * c;
                    float h0 = fast_tanh(v.x + sm[S_BU1 + j]);
                    float h1 = fast_tanh(v.y + sm[S_BU1 + j + 1]);
                    if (valid) {
                        sm[S_H + j * SP + ra]       = h0;
                        sm[S_H + (j + 1) * SP + ra] = h1;
                    }
                }
                PAIR_BAR(group);
                // u2
                mmC<NUU>(sm + S_H, sm + S_WU2, ra, cb, acc2);
#pragma unroll
                for (int c = 0; c < 2; ++c) {
                    float2 v = unpack2(acc2[c]);
                    int j = cb + 2 * c;
                    float u0 = fast_sigm(v.x + sm[S_BU2 + j]);
                    float u1 = fast_sigm(v.y + sm[S_BU2 + j + 1]);
                    if (valid) {
                        sm[S_U + j * SP + ra]       = u0;
                        sm[S_U + (j + 1) * SP + ra] = u1;
                    }
                }
                PAIR_BAR(group);
                // r1
                mmC<GII>(sm + S_YC, sm + S_WR1, ra, cb, acc2);
#pragma unroll
                for (int c = 0; c < 2; ++c) {
                    float2 v = unpack2(acc2[c]);
                    int j = cb + 2 * c;
                    float h0 = fast_tanh(v.x + sm[S_BR1 + j]);
                    float h1 = fast_tanh(v.y + sm[S_BR1 + j + 1]);
                    if (valid) {
                        sm[S_H + j * SP + ra]       = h0;
                        sm[S_H + (j + 1) * SP + ra] = h1;
                    }
                }
                PAIR_BAR(group);
                // r2 -> YC[0:64] = y1 * r
                mmC<NUU>(sm + S_H, sm + S_WR2, ra, cb, acc2);
#pragma unroll
                for (int c = 0; c < 2; ++c) {
                    float2 v = unpack2(acc2[c]);
                    int j = cb + 2 * c;
                    float rg0 = fast_sigm(v.x + sm[S_BR2 + j]);
                    float rg1 = fast_sigm(v.y + sm[S_BR2 + j + 1]);
                    if (valid) {
                        sm[S_YC + j * SP + ra]       = sm[S_Y + j * SP + ra] * rg0;
                        sm[S_YC + (j + 1) * SP + ra] = sm[S_Y + (j + 1) * SP + ra] * rg1;
                    }
                }
                PAIR_BAR(group);
                // n1
                mmC<GII>(sm + S_YC, sm + S_WN1, ra, cb, acc2);
#pragma unroll
                for (int c = 0; c < 2; ++c) {
                    float2 v = unpack2(acc2[c]);
                    int j = cb + 2 * c;
                    float h0 = fast_tanh(v.x + sm[S_BN1 + j]);
                    float h1 = fast_tanh(v.y + sm[S_BN1 + j + 1]);
                    if (valid) {
                        sm[S_H + j * SP + ra]       = h0;
                        sm[S_H + (j + 1) * SP + ra] = h1;
                    }
                }
                PAIR_BAR(group);
                // n2 + blend (only write when mask flag set; else keep y1)
                mmC<NUU>(sm + S_H, sm + S_WN2, ra, cb, acc2);
                {
                    const int mf = s_mflag[ra];
#pragma unroll
                    for (int c = 0; c < 2; ++c) {
                        float2 v = unpack2(acc2[c]);
                        int j = cb + 2 * c;
                        float ns0 = v.x + sm[S_BN2 + j];
                        float ns1 = v.y + sm[S_BN2 + j + 1];
                        float u0  = sm[S_U + j * SP + ra];
                        float u1  = sm[S_U + (j + 1) * SP + ra];
                        float y10 = sm[S_Y + j * SP + ra];
                        float y11 = sm[S_Y + (j + 1) * SP + ra];
                        float ny0 = fmaf(1.f - u0, ns0, u0 * y10);
                        float ny1 = fmaf(1.f - u1, ns1, u1 * y11);
                        if (valid && mf) {
                            sm[S_Y + j * SP + ra]       = ny0;
                            sm[S_Y + (j + 1) * SP + ra] = ny1;
                        }
                    }
                }
            }
        }
        __syncthreads();
    }

    // ---- write final prev_y ----
    for (int e = tid; e < 64 * RB; e += NTHR) {
        int j = e >> 5, r = e & 31;
        out_prevy[(size_t)(row_base + r) * 64 + j] = sm[S_Y + j * SP + r];
    }
}

__global__ void lobrm_gather(const int* __restrict__ tsteps,
                             float* __restrict__ out_sel,
                             float* __restrict__ out_ti)
{
    int i = blockIdx.x * blockDim.x + threadIdx.x;
    if (i >= BB * (TT - 1)) return;
    int b = i / (TT - 1);
    int t = i - b * (TT - 1);
    int v0 = tsteps[(size_t)b * TT + t];
    int v1 = tsteps[(size_t)b * TT + t + 1];
    int inv = v0 < 0 ? 0 : (v0 > KK - 2 ? KK - 2 : v0);
    out_sel[i] = g_vol[(size_t)b * KK + inv + 1];
    out_ti[i]  = (float)(v1 - v0);
}

extern "C" void kernel_launch(void* const* d_in, const int* in_sizes, int n_in,
                              void* d_out, int out_size) {
    const float* data = (const float*)d_in[0];
    const int*   ts   = (const int*)d_in[1];
    const float* Wu1 = (const float*)d_in[2];
    const float* bu1 = (const float*)d_in[3];
    const float* Wu2 = (const float*)d_in[4];
    const float* bu2 = (const float*)d_in[5];
    const float* Wr1 = (const float*)d_in[6];
    const float* br1 = (const float*)d_in[7];
    const float* Wr2 = (const float*)d_in[8];
    const float* br2 = (const float*)d_in[9];
    const float* Wn1 = (const float*)d_in[10];
    const float* bn1 = (const float*)d_in[11];
    const float* Wn2 = (const float*)d_in[12];
    const float* bn2 = (const float*)d_in[13];
    const float* Wo1 = (const float*)d_in[14];
    const float* bo1 = (const float*)d_in[15];
    const float* Wo2 = (const float*)d_in[16];
    const float* bo2 = (const float*)d_in[17];
    const float* Wd  = (const float*)d_in[18];
    const float* bd  = (const float*)d_in[19];

    float* out = (float*)d_out;
    float* out_prevy = out;                       // B*64
    float* out_sel   = out + (size_t)BB * LL;     // B*63
    float* out_ti    = out_sel + (size_t)BB * (TT - 1);

    cudaFuncSetAttribute(lobrm_main, cudaFuncAttributeMaxDynamicSharedMemorySize,
                         SMEM_BYTES);
    lobrm_main<<<BB / RB, NTHR, SMEM_BYTES>>>(
        data, ts, Wu1, bu1, Wu2, bu2, Wr1, br1, Wr2, br2,
        Wn1, bn1, Wn2, bn2, Wo1, bo1, Wo2, bo2, Wd, bd, out_prevy);
    lobrm_gather<<<(BB * (TT - 1) + 255) / 256, 256>>>(ts, out_sel, out_ti);
}

// round 6
// speedup vs baseline: 1.8009x; 1.2274x over previous
#include <cuda_runtime.h>
#include <math.h>

// Problem constants
#define BB   4096
#define TT   64
#define DD   100
#define FF   50
#define LL   64
#define NUU  64
#define KK   128
#define GII  114   // F + L
#define RB   32    // rows per CTA
#define NTHR 256
#define SPC  34    // col-major stride (even -> LDS.64 row pairs aligned)
#define SYC  116   // YC row-major stride (29 quads * 4)
#define SH2  68    // H2/U2 row-major stride

// ---- dynamic shared memory layout (floats) ----
#define S_WU1 0
#define S_WR1 (S_WU1 + GII*64)
#define S_WN1 (S_WR1 + GII*64)
#define S_WO1 (S_WN1 + GII*64)
#define S_WU2 (S_WO1 + 64*64)
#define S_WR2 (S_WU2 + 64*64)
#define S_WN2 (S_WR2 + 64*64)
#define S_WO2 (S_WN2 + 64*64)
#define S_WD  (S_WO2 + 64*64)
#define S_BU1 (S_WD + 64)
#define S_BU2 (S_BU1 + 64)
#define S_BR1 (S_BU2 + 64)
#define S_BR2 (S_BR1 + 64)
#define S_BN1 (S_BR2 + 64)
#define S_BN2 (S_BN1 + 64)
#define S_BO1 (S_BN2 + 64)
#define S_BO2 (S_BO1 + 64)
#define S_Y   (S_BO2 + 64)            // 42944: col-major 64 x SPC
#define S_H   (S_Y  + 64*SPC)         // 45120: o-path H col-major 64xSPC,
                                      //        ALIASED as chain H2 row-major 32xSH2
#define S_U2  (S_H  + 64*SPC)         // 47296: row-major 32 x SH2
#define S_YC  (S_U2 + RB*SH2)         // 49472: row-major 32 x SYC
#define S_PV  (S_YC + RB*SYC)         // 53184: 8 x 32 vol partials
#define S_ACTB (S_PV + 8*32)          // 53440: act table (4096 bytes = 1024 floats)
#define S_IDXB (S_ACTB + 1024)        // 54464: idx table (4096 bytes)
#define S_END (S_IDXB + 1024)         // 55488 floats
#define SMEM_BYTES (S_END * 4)        // 221952 bytes

typedef unsigned long long u64;

// scratch: per-row per-step volume output
__device__ float g_vol[BB * KK];

// ---- fast math primitives ----
__device__ __forceinline__ float fast_rcp(float x) {
    float r; asm("rcp.approx.f32 %0, %1;" : "=f"(r) : "f"(x)); return r;
}
__device__ __forceinline__ float fast_ex2(float x) {
    float r; asm("ex2.approx.f32 %0, %1;" : "=f"(r) : "f"(x)); return r;
}
__device__ __forceinline__ float fast_sigm(float x) {
    return fast_rcp(1.0f + fast_ex2(-1.4426950408889634f * x));
}
__device__ __forceinline__ float fast_tanh(float x) {
    return fmaf(2.0f, fast_rcp(1.0f + fast_ex2(-2.8853900817779268f * x)), -1.0f);
}

// ---- packed f32x2 primitives ----
__device__ __forceinline__ u64 pack2(float x) {
    u64 r; asm("mov.b64 %0, {%1, %1};" : "=l"(r) : "f"(x)); return r;
}
__device__ __forceinline__ void fma2(u64& d, u64 a, u64 b) {
    asm("fma.rn.f32x2 %0, %1, %2, %0;" : "+l"(d) : "l"(a), "l"(b));
}
__device__ __forceinline__ float2 unpack2(u64 v) {
    float2 f; asm("mov.b64 {%0, %1}, %2;" : "=f"(f.x), "=f"(f.y) : "l"(v)); return f;
}

// All-row GEMM, col-major A (stride SPC): thread = rows (r0,r0+1) x cols [cq,cq+4).
// acc[0]=r0x{cq,cq+1} acc[1]=r0x{cq+2,cq+3} acc[2]=r1x{cq,cq+1} acc[3]=r1x{cq+2,cq+3}
template<int KI>
__device__ __forceinline__ void mmA(const float* __restrict__ A,
                                    const float* __restrict__ W,
                                    int r0, int cq, u64 (&acc)[4]) {
    acc[0] = acc[1] = acc[2] = acc[3] = 0ULL;
#pragma unroll 4
    for (int k = 0; k < KI; ++k) {
        float2 a = *reinterpret_cast<const float2*>(A + k * SPC + r0);
        ulonglong2 w = *reinterpret_cast<const ulonglong2*>(W + k * 64 + cq);
        u64 ax = pack2(a.x), ay = pack2(a.y);
        fma2(acc[0], ax, w.x);
        fma2(acc[1], ax, w.y);
        fma2(acc[2], ay, w.x);
        fma2(acc[3], ay, w.y);
    }
}

// Compacted GEMM, row-major A (stride AS): thread = row ra x cols [cb,cb+4).
template<int NQ, int AS>
__device__ __forceinline__ void mmC(const float* __restrict__ A,
                                    const float* __restrict__ W,
                                    int ra, int cb, u64 (&acc)[2]) {
    acc[0] = acc[1] = 0ULL;
    const float4* ap = reinterpret_cast<const float4*>(A + ra * AS);
#pragma unroll 2
    for (int q = 0; q < NQ; ++q) {
        float4 a4 = ap[q];
        const float* W4 = W + 4 * q * 64 + cb;
        {
            u64 aa = pack2(a4.x);
            ulonglong2 w = *reinterpret_cast<const ulonglong2*>(W4);
            fma2(acc[0], aa, w.x); fma2(acc[1], aa, w.y);
        }
        {
            u64 aa = pack2(a4.y);
            ulonglong2 w = *reinterpret_cast<const ulonglong2*>(W4 + 64);
            fma2(acc[0], aa, w.x); fma2(acc[1], aa, w.y);
        }
        {
            u64 aa = pack2(a4.z);
            ulonglong2 w = *reinterpret_cast<const ulonglong2*>(W4 + 128);
            fma2(acc[0], aa, w.x); fma2(acc[1], aa, w.y);
        }
        {
            u64 aa = pack2(a4.w);
            ulonglong2 w = *reinterpret_cast<const ulonglong2*>(W4 + 192);
            fma2(acc[0], aa, w.x); fma2(acc[1], aa, w.y);
        }
    }
}

#define PAIR_BAR(grp) asm volatile("bar.sync %0, 64;" :: "r"(1 + (grp)) : "memory")

__global__ void __launch_bounds__(NTHR, 1) lobrm_main(
    const float* __restrict__ data, const int* __restrict__ tsteps,
    const float* __restrict__ Wu1, const float* __restrict__ bu1,
    const float* __restrict__ Wu2, const float* __restrict__ bu2,
    const float* __restrict__ Wr1, const float* __restrict__ br1,
    const float* __restrict__ Wr2, const float* __restrict__ br2,
    const float* __restrict__ Wn1, const float* __restrict__ bn1,
    const float* __restrict__ Wn2, const float* __restrict__ bn2,
    const float* __restrict__ Wo1, const float* __restrict__ bo1,
    const float* __restrict__ Wo2, const float* __restrict__ bo2,
    const float* __restrict__ Wd,  const float* __restrict__ bd,
    float* __restrict__ out_prevy)
{
    extern __shared__ float sm[];
    unsigned char* s_act  = reinterpret_cast<unsigned char*>(sm + S_ACTB); // [KK][RB]
    unsigned char* s_idxk = reinterpret_cast<unsigned char*>(sm + S_IDXB); // [KK][RB]
    __shared__ int   s_nact[KK];
    __shared__ int   s_morflag[RB];   // any-mask-nonzero flag (benign race)
    __shared__ int   s_mflag[RB];
    __shared__ float s_bd;

    const int tid = threadIdx.x;
    const int row_base = blockIdx.x * RB;

    // ---- load weights + biases into smem ----
    {
        auto cpy = [&](int off, const float* src, int n) {
            for (int i = tid; i < n; i += NTHR) sm[off + i] = src[i];
        };
        cpy(S_WU1, Wu1, GII*64); cpy(S_WR1, Wr1, GII*64); cpy(S_WN1, Wn1, GII*64);
        cpy(S_WO1, Wo1, 64*64);  cpy(S_WU2, Wu2, 64*64);  cpy(S_WR2, Wr2, 64*64);
        cpy(S_WN2, Wn2, 64*64);  cpy(S_WO2, Wo2, 64*64);
        cpy(S_WD, Wd, 64);
        cpy(S_BU1, bu1, 64); cpy(S_BU2, bu2, 64);
        cpy(S_BR1, br1, 64); cpy(S_BR2, br2, 64);
        cpy(S_BN1, bn1, 64); cpy(S_BN2, bn2, 64);
        cpy(S_BO1, bo1, 64); cpy(S_BO2, bo2, 64);
    }
    if (tid == 0) s_bd = bd[0];

    // zero state Y and YC (incl. k-pad cols 114,115)
    for (int e = tid; e < 64 * SPC; e += NTHR) sm[S_Y + e] = 0.f;
    for (int e = tid; e < RB * SYC; e += NTHR) sm[S_YC + e] = 0.f;

    // ---- warp 0: presence masks, per-step active lists + event indices ----
    if (tid < RB) {
        const int r = tid;
        unsigned m0 = 0, m1 = 0, m2 = 0, m3 = 0;
        const int* tp = tsteps + (size_t)(row_base + r) * TT;
        for (int t = 0; t < TT; ++t) {
            int v = tp[t];           // in [0, 128)
            unsigned bit = 1u << (v & 31);
            int w = v >> 5;
            if (w == 0) m0 |= bit; else if (w == 1) m1 |= bit;
            else if (w == 2) m2 |= bit; else m3 |= bit;
        }
        const unsigned below = (r == 31) ? 0x7fffffffu : ((1u << r) - 1u);
        int c = 0;
        for (int k = 0; k < KK; ++k) {
            unsigned mk = (k < 32) ? m0 : (k < 64) ? m1 : (k < 96) ? m2 : m3;
            int bit = (mk >> (k & 31)) & 1;
            unsigned bal = __ballot_sync(0xffffffffu, bit);
            if (r == 0) s_nact[k] = __popc(bal);
            s_idxk[k * RB + r] = (unsigned char)c;
            if (bit) s_act[k * RB + __popc(bal & below)] = (unsigned char)r;
            c += bit;
        }
        s_morflag[r] = 0;
    }
    __syncthreads();

    const int lane = tid & 31;
    const int wid  = tid >> 5;
    // mmA mapping: rows (r0, r0+1), cols [cq, cq+4)
    const int r0 = 2 * (lane & 15);
    const int cq = 8 * wid + 4 * (lane >> 4);
    // chain mapping: group (2 warps) = 4 rows x 64 cols
    const int group = wid >> 1;
    const int half  = wid & 1;
    const int p  = lane >> 3;       // row slot within group
    const int g  = lane & 7;        // col quad
    const int cb = 32 * half + 4 * g;

    u64 acc4[4];
    u64 acc2[2];

    for (int k = 0; k < KK; ++k) {
        const int nact = s_nact[k];
        const unsigned char* actk = s_act + k * RB;

        // ================= P1: feat prefetch + vol partial + o1 =================
        const int nel = nact * DD;
        float fv[13];
#pragma unroll
        for (int it = 0; it < 13; ++it) {
            int e = tid + it * NTHR;
            fv[it] = 0.f;
            if (e < nel) {
                int q = e / DD, f = e - q * DD;
                int ra = actk[q];
                int idx = s_idxk[k * RB + ra];
                fv[it] = data[((size_t)(row_base + ra) * TT + idx) * DD + f];
            }
        }
        // vol partials from prev_y
        {
            float pv = 0.f;
#pragma unroll
            for (int i = 0; i < 8; ++i) {
                int ii = wid * 8 + i;
                pv = fmaf(sm[S_Y + ii * SPC + lane], sm[S_WD + ii], pv);
            }
            sm[S_PV + wid * 32 + lane] = pv;
        }
        // o1: H = tanh(Y @ Wo1 + bo1)   (col-major H)
        mmA<64>(sm + S_Y, sm + S_WO1, r0, cq, acc4);
        {
            float2 a0 = unpack2(acc4[0]), a1 = unpack2(acc4[1]);
            float2 b0 = unpack2(acc4[2]), b1 = unpack2(acc4[3]);
            float vr0[4] = {a0.x, a0.y, a1.x, a1.y};
            float vr1[4] = {b0.x, b0.y, b1.x, b1.y};
#pragma unroll
            for (int cc = 0; cc < 4; ++cc) {
                int j = cq + cc; float bj = sm[S_BO1 + j];
                float2 hv = { fast_tanh(vr0[cc] + bj), fast_tanh(vr1[cc] + bj) };
                *reinterpret_cast<float2*>(sm + S_H + j * SPC + r0) = hv;
            }
        }
        // store fetched feat + mask flags (row-major YC)
#pragma unroll
        for (int it = 0; it < 13; ++it) {
            int e = tid + it * NTHR;
            if (e < nel) {
                int q = e / DD, f = e - q * DD;
                int ra = actk[q];
                if (f < FF) sm[S_YC + ra * SYC + 64 + f] = fv[it];
                else if (fv[it] != 0.f) s_morflag[ra] = 1;   // benign race
            }
        }
        __syncthreads();

        // ================= P2: o2 -> y1 for ALL rows + vol finalize =================
        mmA<64>(sm + S_H, sm + S_WO2, r0, cq, acc4);
        {
            float2 a0 = unpack2(acc4[0]), a1 = unpack2(acc4[1]);
            float2 b0 = unpack2(acc4[2]), b1 = unpack2(acc4[3]);
            float vr0[4] = {a0.x, a0.y, a1.x, a1.y};
            float vr1[4] = {b0.x, b0.y, b1.x, b1.y};
#pragma unroll
            for (int cc = 0; cc < 4; ++cc) {
                int j = cq + cc; float bj = sm[S_BO2 + j];
                float2 yv = *reinterpret_cast<const float2*>(sm + S_Y + j * SPC + r0);
                float n0 = vr0[cc] + bj + yv.x;
                float n1 = vr1[cc] + bj + yv.y;
                *reinterpret_cast<float2*>(sm + S_Y + j * SPC + r0) = make_float2(n0, n1);
                sm[S_YC + r0 * SYC + j]       = n0;
                sm[S_YC + (r0 + 1) * SYC + j] = n1;
            }
        }
        if (tid < RB) {
            float v = s_bd;
#pragma unroll
            for (int seg = 0; seg < 8; ++seg) v += sm[S_PV + seg * 32 + tid];
            g_vol[(size_t)(row_base + tid) * KK + k] = v;
            s_mflag[tid] = s_morflag[tid];
            s_morflag[tid] = 0;
        }
        __syncthreads();

        // ================= fused compacted u/r/n chain (row-major A) =================
        for (int base = 0; base < nact; base += 16) {
            const int slot = base + 4 * group + p;
            const bool valid = slot < nact;
            const int ra = actk[slot & 31] & 31;
            const bool wact = (base + 4 * group) < nact;   // pair-uniform
            if (wact) {
                // u1: H2 = tanh(YC @ Wu1 + bu1)
                mmC<29, SYC>(sm + S_YC, sm + S_WU1, ra, cb, acc2);
                {
                    float2 v0 = unpack2(acc2[0]), v1 = unpack2(acc2[1]);
                    float4 hw;
                    hw.x = fast_tanh(v0.x + sm[S_BU1 + cb]);
                    hw.y = fast_tanh(v0.y + sm[S_BU1 + cb + 1]);
                    hw.z = fast_tanh(v1.x + sm[S_BU1 + cb + 2]);
                    hw.w = fast_tanh(v1.y + sm[S_BU1 + cb + 3]);
                    if (valid) *reinterpret_cast<float4*>(sm + S_H + ra * SH2 + cb) = hw;
                }
                PAIR_BAR(group);
                // u2: U2 = sigmoid(H2 @ Wu2 + bu2)
                mmC<16, SH2>(sm + S_H, sm + S_WU2, ra, cb, acc2);
                {
                    float2 v0 = unpack2(acc2[0]), v1 = unpack2(acc2[1]);
                    float4 uw;
                    uw.x = fast_sigm(v0.x + sm[S_BU2 + cb]);
                    uw.y = fast_sigm(v0.y + sm[S_BU2 + cb + 1]);
                    uw.z = fast_sigm(v1.x + sm[S_BU2 + cb + 2]);
                    uw.w = fast_sigm(v1.y + sm[S_BU2 + cb + 3]);
                    if (valid) *reinterpret_cast<float4*>(sm + S_U2 + ra * SH2 + cb) = uw;
                }
                PAIR_BAR(group);
                // r1: H2 = tanh(YC @ Wr1 + br1)
                mmC<29, SYC>(sm + S_YC, sm + S_WR1, ra, cb, acc2);
                {
                    float2 v0 = unpack2(acc2[0]), v1 = unpack2(acc2[1]);
                    float4 hw;
                    hw.x = fast_tanh(v0.x + sm[S_BR1 + cb]);
                    hw.y = fast_tanh(v0.y + sm[S_BR1 + cb + 1]);
                    hw.z = fast_tanh(v1.x + sm[S_BR1 + cb + 2]);
                    hw.w = fast_tanh(v1.y + sm[S_BR1 + cb + 3]);
                    if (valid) *reinterpret_cast<float4*>(sm + S_H + ra * SH2 + cb) = hw;
                }
                PAIR_BAR(group);
                // r2: YC[0:64] = y1 * sigmoid(H2 @ Wr2 + br2)
                mmC<16, SH2>(sm + S_H, sm + S_WR2, ra, cb, acc2);
                {
                    float2 v0 = unpack2(acc2[0]), v1 = unpack2(acc2[1]);
                    float rg[4] = { fast_sigm(v0.x + sm[S_BR2 + cb]),
                                    fast_sigm(v0.y + sm[S_BR2 + cb + 1]),
                                    fast_sigm(v1.x + sm[S_BR2 + cb + 2]),
                                    fast_sigm(v1.y + sm[S_BR2 + cb + 3]) };
                    float4 yc;
                    yc.x = sm[S_Y + (cb    ) * SPC + ra] * rg[0];
                    yc.y = sm[S_Y + (cb + 1) * SPC + ra] * rg[1];
                    yc.z = sm[S_Y + (cb + 2) * SPC + ra] * rg[2];
                    yc.w = sm[S_Y + (cb + 3) * SPC + ra] * rg[3];
                    if (valid) *reinterpret_cast<float4*>(sm + S_YC + ra * SYC + cb) = yc;
                }
                PAIR_BAR(group);
                // n1: H2 = tanh(YC @ Wn1 + bn1)
                mmC<29, SYC>(sm + S_YC, sm + S_WN1, ra, cb, acc2);
                {
                    float2 v0 = unpack2(acc2[0]), v1 = unpack2(acc2[1]);
                    float4 hw;
                    hw.x = fast_tanh(v0.x + sm[S_BN1 + cb]);
                    hw.y = fast_tanh(v0.y + sm[S_BN1 + cb + 1]);
                    hw.z = fast_tanh(v1.x + sm[S_BN1 + cb + 2]);
                    hw.w = fast_tanh(v1.y + sm[S_BN1 + cb + 3]);
                    if (valid) *reinterpret_cast<float4*>(sm + S_H + ra * SH2 + cb) = hw;
                }
                PAIR_BAR(group);
                // n2 + blend (only overwrite Y when mask flag set; else keep y1)
                mmC<16, SH2>(sm + S_H, sm + S_WN2, ra, cb, acc2);
                {
                    const int mf = s_mflag[ra];
                    float2 v0 = unpack2(acc2[0]), v1 = unpack2(acc2[1]);
                    float ns[4] = { v0.x + sm[S_BN2 + cb],
                                    v0.y + sm[S_BN2 + cb + 1],
                                    v1.x + sm[S_BN2 + cb + 2],
                                    v1.y + sm[S_BN2 + cb + 3] };
                    float4 uq = *reinterpret_cast<const float4*>(sm + S_U2 + ra * SH2 + cb);
                    float uu[4] = {uq.x, uq.y, uq.z, uq.w};
#pragma unroll
                    for (int cc = 0; cc < 4; ++cc) {
                        int j = cb + cc;
                        float y1 = sm[S_Y + j * SPC + ra];
                        float ny = fmaf(1.f - uu[cc], ns[cc], uu[cc] * y1);
                        if (valid && mf) sm[S_Y + j * SPC + ra] = ny;
                    }
                }
            }
        }
        __syncthreads();
    }

    // ---- write final prev_y ----
    for (int e = tid; e < 64 * RB; e += NTHR) {
        int j = e >> 5, r = e & 31;
        out_prevy[(size_t)(row_base + r) * 64 + j] = sm[S_Y + j * SPC + r];
    }
}

__global__ void lobrm_gather(const int* __restrict__ tsteps,
                             float* __restrict__ out_sel,
                             float* __restrict__ out_ti)
{
    int i = blockIdx.x * blockDim.x + threadIdx.x;
    if (i >= BB * (TT - 1)) return;
    int b = i / (TT - 1);
    int t = i - b * (TT - 1);
    int v0 = tsteps[(size_t)b * TT + t];
    int v1 = tsteps[(size_t)b * TT + t + 1];
    int inv = v0 < 0 ? 0 : (v0 > KK - 2 ? KK - 2 : v0);
    out_sel[i] = g_vol[(size_t)b * KK + inv + 1];
    out_ti[i]  = (float)(v1 - v0);
}

extern "C" void kernel_launch(void* const* d_in, const int* in_sizes, int n_in,
                              void* d_out, int out_size) {
    const float* data = (const float*)d_in[0];
    const int*   ts   = (const int*)d_in[1];
    const float* Wu1 = (const float*)d_in[2];
    const float* bu1 = (const float*)d_in[3];
    const float* Wu2 = (const float*)d_in[4];
    const float* bu2 = (const float*)d_in[5];
    const float* Wr1 = (const float*)d_in[6];
    const float* br1 = (const float*)d_in[7];
    const float* Wr2 = (const float*)d_in[8];
    const float* br2 = (const float*)d_in[9];
    const float* Wn1 = (const float*)d_in[10];
    const float* bn1 = (const float*)d_in[11];
    const float* Wn2 = (const float*)d_in[12];
    const float* bn2 = (const float*)d_in[13];
    const float* Wo1 = (const float*)d_in[14];
    const float* bo1 = (const float*)d_in[15];
    const float* Wo2 = (const float*)d_in[16];
    const float* bo2 = (const float*)d_in[17];
    const float* Wd  = (const float*)d_in[18];
    const float* bd  = (const float*)d_in[19];

    float* out = (float*)d_out;
    float* out_prevy = out;                       // B*64
    float* out_sel   = out + (size_t)BB * LL;     // B*63
    float* out_ti    = out_sel + (size_t)BB * (TT - 1);

    cudaFuncSetAttribute(lobrm_main, cudaFuncAttributeMaxDynamicSharedMemorySize,
                         SMEM_BYTES);
    lobrm_main<<<BB / RB, NTHR, SMEM_BYTES>>>(
        data, ts, Wu1, bu1, Wu2, bu2, Wr1, br1, Wr2, br2,
        Wn1, bn1, Wn2, bn2, Wo1, bo1, Wo2, bo2, Wd, bd, out_prevy);
    lobrm_gather<<<(BB * (TT - 1) + 255) / 256, 256>>>(ts, out_sel, out_ti);
}